// round 4
// baseline (speedup 1.0000x reference)
#include <cuda_runtime.h>

#define RCH 64
#define GCH 128
#define ACH 80
#define SCH 64
#define TT 8192
#define BB 8
#define NPOS (BB*TT)          // 65536
#define NLAYERS 30
#define POSB 128              // positions per block
#define PAIRS 64              // position-pairs per block
#define THR 512
#define KPACK 336             // 192 conv + 80 aux + 64 out
#define SMEM_LAYER (64*128*8 + 64*64*8)   // 65536+32768 = 98304

__device__ float g_xa[BB*RCH*TT];
__device__ float g_xb[BB*RCH*TT];
__device__ float g_skip[BB*SCH*TT];

typedef unsigned long long ull;

// packed duplicated weights: [layer][k][ch] = (w,w), k: 0..191 conv(tap*64+ci),
// 192..271 aux j, 272..335 out j ; ch = 0..127
__device__ ull g_pk[(size_t)NLAYERS * KPACK * 128];

static __device__ __forceinline__ ull pk2(float lo, float hi) {
    ull r; asm("mov.b64 %0, {%1, %2};" : "=l"(r) : "f"(lo), "f"(hi)); return r;
}
static __device__ __forceinline__ void upk2(ull v, float& lo, float& hi) {
    asm("mov.b64 {%0, %1}, %2;" : "=f"(lo), "=f"(hi) : "l"(v));
}
static __device__ __forceinline__ void fma2(ull& acc, ull w, ull x) {
    asm("fma.rn.f32x2 %0, %1, %2, %0;" : "+l"(acc) : "l"(w), "l"(x));
}
static __device__ __forceinline__ ull mul2(ull a, ull b) {
    ull r; asm("mul.rn.f32x2 %0, %1, %2;" : "=l"(r) : "l"(a), "l"(b)); return r;
}
static __device__ __forceinline__ ull add2(ull a, ull b) {
    ull r; asm("add.rn.f32x2 %0, %1, %2;" : "=l"(r) : "l"(a), "l"(b)); return r;
}
static __device__ __forceinline__ float tanhapx(float x) {
    float r; asm("tanh.approx.f32 %0, %1;" : "=f"(r) : "f"(x)); return r;
}
static __device__ __forceinline__ float gatef(float a, float b) {
    return tanhapx(a) * (0.5f * tanhapx(0.5f * b) + 0.5f);
}

// ---------------------------------------------------------------------------
// one-shot weight repack: scalar -> duplicated u64 in staging-friendly layout
// ---------------------------------------------------------------------------
__global__ void k_prep(const float* __restrict__ cw, const float* __restrict__ aw,
                       const float* __restrict__ ow) {
    int idx = blockIdx.x * blockDim.x + threadIdx.x;
    if (idx >= NLAYERS * KPACK * 128) return;
    int ch = idx & 127;
    int k  = (idx >> 7) % KPACK;
    int l  = idx / (KPACK * 128);
    float v;
    if (k < 192) {
        int tap = k >> 6, ci = k & 63;
        v = cw[((size_t)l * GCH + ch) * (RCH * 3) + ci * 3 + tap];
    } else if (k < 272) {
        v = aw[((size_t)l * GCH + ch) * ACH + (k - 192)];
    } else {
        v = ow[((size_t)l * GCH + ch) * (GCH / 2) + (k - 272)];
    }
    g_pk[idx] = pk2(v, v);
}

// ---------------------------------------------------------------------------
__global__ void k_first(const float* __restrict__ x,
                        const float* __restrict__ fw,
                        const float* __restrict__ fb) {
    int idx = blockIdx.x * blockDim.x + threadIdx.x;
    int r = idx >> 16;
    int p = idx & (NPOS - 1);
    int b = p >> 13;
    int t = p & (TT - 1);
    float v = fw[r] * x[p] + fb[r];
    g_xa[(b * RCH + r) * TT + t] = v;
    g_skip[(b * SCH + r) * TT + t] = 0.f;
}

// ---------------------------------------------------------------------------
// inner GEMM block: 16 fma2 per k. Weights are warp-uniform broadcasts.
// ---------------------------------------------------------------------------
static __device__ __forceinline__ void gemm_acc(ull (&acc)[8][2],
        const ull* __restrict__ wk, const ull* __restrict__ xk,
        int K, int c4, int lane) {
#pragma unroll 2
    for (int k = 0; k < K; k++) {
        ulonglong2 xx = *(const ulonglong2*)(xk + k * PAIRS + 2 * lane);
        const ull* w = wk + k * 128 + c4;
        ulonglong2 w01 = *(const ulonglong2*)(w);
        ulonglong2 w23 = *(const ulonglong2*)(w + 2);
        ulonglong2 w45 = *(const ulonglong2*)(w + 64);
        ulonglong2 w67 = *(const ulonglong2*)(w + 66);
        fma2(acc[0][0], (ull)w01.x, (ull)xx.x); fma2(acc[0][1], (ull)w01.x, (ull)xx.y);
        fma2(acc[1][0], (ull)w01.y, (ull)xx.x); fma2(acc[1][1], (ull)w01.y, (ull)xx.y);
        fma2(acc[2][0], (ull)w23.x, (ull)xx.x); fma2(acc[2][1], (ull)w23.x, (ull)xx.y);
        fma2(acc[3][0], (ull)w23.y, (ull)xx.x); fma2(acc[3][1], (ull)w23.y, (ull)xx.y);
        fma2(acc[4][0], (ull)w45.x, (ull)xx.x); fma2(acc[4][1], (ull)w45.x, (ull)xx.y);
        fma2(acc[5][0], (ull)w45.y, (ull)xx.x); fma2(acc[5][1], (ull)w45.y, (ull)xx.y);
        fma2(acc[6][0], (ull)w67.x, (ull)xx.x); fma2(acc[6][1], (ull)w67.x, (ull)xx.y);
        fma2(acc[7][0], (ull)w67.y, (ull)xx.x); fma2(acc[7][1], (ull)w67.y, (ull)xx.y);
    }
}

// ---------------------------------------------------------------------------
// fused layer: warp g owns gate-pairs {4g..4g+3}; lane owns pos pairs
// {2*lane, 2*lane+1} (positions 4*lane .. 4*lane+3).
// ---------------------------------------------------------------------------
__global__ void __launch_bounds__(THR, 2)
k_layer(int l, int d, int flip,
        const float* __restrict__ conv_b, const float* __restrict__ out_b,
        const float* __restrict__ cond,   const float* __restrict__ mask) {
    extern __shared__ char smraw[];
    ull* wsh = (ull*)smraw;                       // up to [64][128]
    ull* xb  = (ull*)(smraw + 64 * 128 * 8);      // up to [64][64]

    const float* xin  = flip ? g_xb : g_xa;
    float*       xout = flip ? g_xa : g_xb;

    const int tid  = threadIdx.x;
    const int wid  = tid >> 5;
    const int lane = tid & 31;
    const int c4   = 4 * wid;
    const int p0   = blockIdx.x * POSB;
    const int b    = p0 >> 13;
    const int tb   = p0 & (TT - 1);

    const ull* pk = g_pk + (size_t)l * KPACK * 128;

    // ===== accumulators (conv bias) =========================================
    ull acc[8][2];
    const float* cbp = conv_b + l * GCH;
#pragma unroll
    for (int i = 0; i < 4; i++) {
        ull plo = pk2(cbp[c4 + i], cbp[c4 + i]);
        ull phi = pk2(cbp[64 + c4 + i], cbp[64 + c4 + i]);
        acc[i][0] = plo; acc[i][1] = plo;
        acc[4 + i][0] = phi; acc[4 + i][1] = phi;
    }

    // ===== dilated conv: 3 taps =============================================
#pragma unroll 1
    for (int tap = 0; tap < 3; ++tap) {
        const int off = (tap - 1) * d;
        __syncthreads();
        // stage weights for this tap: 64x128 ull
        {
            const ulonglong2* src = (const ulonglong2*)(pk + tap * 64 * 128);
            ulonglong2* dst = (ulonglong2*)wsh;
#pragma unroll
            for (int r = 0; r < 8; r++) dst[tid + r * THR] = src[tid + r * THR];
        }
        // stage x tile: [64 ci][64 pairs]
        for (int idx = tid; idx < RCH * PAIRS; idx += THR) {
            int ci = idx >> 6, pr = idx & 63;
            const float* xrow = xin + (size_t)(b * RCH + ci) * TT;
            int t0 = tb + 2 * pr + off;
            float v0 = ((unsigned)t0 < TT) ? xrow[t0] : 0.f;
            float v1 = ((unsigned)(t0 + 1) < TT) ? xrow[t0 + 1] : 0.f;
            xb[idx] = pk2(v0, v1);
        }
        __syncthreads();
        gemm_acc(acc, wsh, xb, RCH, c4, lane);
    }

    // ===== aux: 2 chunks of 40 ==============================================
#pragma unroll 1
    for (int ch = 0; ch < 2; ch++) {
        __syncthreads();
        {
            const ulonglong2* src = (const ulonglong2*)(pk + (192 + 40 * ch) * 128);
            ulonglong2* dst = (ulonglong2*)wsh;
#pragma unroll
            for (int r = 0; r < 5; r++) dst[tid + r * THR] = src[tid + r * THR];
        }
        for (int idx = tid; idx < 40 * PAIRS; idx += THR) {
            int j = idx >> 6, pr = idx & 63;
            float2 v = *(const float2*)(cond + (size_t)(b * ACH + 40 * ch + j) * TT
                                        + tb + 2 * pr);
            xb[idx] = pk2(v.x, v.y);
        }
        __syncthreads();
        gemm_acc(acc, wsh, xb, 40, c4, lane);
    }

    // ===== gate -> zsh (xb), stage out weights ==============================
    __syncthreads();
#pragma unroll
    for (int i = 0; i < 4; i++) {
        float a0, a1, b0, b1, c0, c1, d1, d2;
        upk2(acc[i][0], a0, a1);  upk2(acc[4 + i][0], b0, b1);
        upk2(acc[i][1], c0, c1);  upk2(acc[4 + i][1], d1, d2);
        ulonglong2 zz;
        zz.x = pk2(gatef(a0, b0), gatef(a1, b1));
        zz.y = pk2(gatef(c0, d1), gatef(c1, d2));
        *(ulonglong2*)(xb + (c4 + i) * PAIRS + 2 * lane) = zz;
    }
    {
        const ulonglong2* src = (const ulonglong2*)(pk + 272 * 128);
        ulonglong2* dst = (ulonglong2*)wsh;
#pragma unroll
        for (int r = 0; r < 8; r++) dst[tid + r * THR] = src[tid + r * THR];
    }
    __syncthreads();

    // ===== out projection ====================================================
    ull oacc[8][2];
    const float* obp = out_b + l * (RCH + SCH);
#pragma unroll
    for (int i = 0; i < 4; i++) {
        ull plo = pk2(obp[c4 + i], obp[c4 + i]);
        ull phi = pk2(obp[64 + c4 + i], obp[64 + c4 + i]);
        oacc[i][0] = plo; oacc[i][1] = plo;
        oacc[4 + i][0] = phi; oacc[4 + i][1] = phi;
    }
    gemm_acc(oacc, wsh, xb, GCH / 2, c4, lane);

    // ===== mask, residual, skip (128-bit packed) ============================
    const int tpos = tb + 4 * lane;
    ulonglong2 mm = *(const ulonglong2*)(mask + p0 + 4 * lane);
#pragma unroll
    for (int i = 0; i < 4; i++) {
        size_t xi = ((size_t)(b * RCH + c4 + i) << 13) + tpos;
        ulonglong2 xv = *(const ulonglong2*)(xin + xi);
        ulonglong2 ov;
        ov.x = add2((ull)xv.x, mul2(oacc[i][0], (ull)mm.x));
        ov.y = add2((ull)xv.y, mul2(oacc[i][1], (ull)mm.y));
        *(ulonglong2*)(xout + xi) = ov;

        size_t si = ((size_t)(b * SCH + c4 + i) << 13) + tpos;
        ulonglong2 sv = *(const ulonglong2*)(g_skip + si);
        ulonglong2 so;
        so.x = add2((ull)sv.x, mul2(oacc[4 + i][0], (ull)mm.x));
        so.y = add2((ull)sv.y, mul2(oacc[4 + i][1], (ull)mm.y));
        *(ulonglong2*)(g_skip + si) = so;
    }
}

// ---------------------------------------------------------------------------
__global__ void k_last(const float* __restrict__ w1, const float* __restrict__ b1,
                       const float* __restrict__ w2, const float* __restrict__ b2,
                       float* __restrict__ out) {
    __shared__ float w1t[64 * 64];
    __shared__ float w2s[64];
    __shared__ float b1s[64];
    const int tid = threadIdx.x;
    for (int idx = tid; idx < 64 * 64; idx += 256) {
        int i = idx >> 6, j = idx & 63;
        w1t[i * 64 + j] = w1[j * 64 + i];
    }
    if (tid < 64) { w2s[tid] = w2[tid]; b1s[tid] = b1[tid]; }
    __syncthreads();

    const int p = blockIdx.x * 256 + tid;
    const int b = p >> 13;
    const int t = p & (TT - 1);

    float acc[64];
#pragma unroll
    for (int j = 0; j < 64; j++) acc[j] = b1s[j];

    const float* sp = g_skip + (size_t)b * SCH * TT + t;
    for (int i = 0; i < 64; i++) {
        float sv = fmaxf(sp[i * TT], 0.f);
#pragma unroll
        for (int j = 0; j < 64; j += 4) {
            float4 w = *(const float4*)(w1t + i * 64 + j);
            acc[j]     = fmaf(w.x, sv, acc[j]);
            acc[j + 1] = fmaf(w.y, sv, acc[j + 1]);
            acc[j + 2] = fmaf(w.z, sv, acc[j + 2]);
            acc[j + 3] = fmaf(w.w, sv, acc[j + 3]);
        }
    }
    float y = b2[0];
#pragma unroll
    for (int j = 0; j < 64; j++) y = fmaf(w2s[j], fmaxf(acc[j], 0.f), y);
    out[p] = y;
}

// ---------------------------------------------------------------------------
extern "C" void kernel_launch(void* const* d_in, const int* in_sizes, int n_in,
                              void* d_out, int out_size) {
    const float* x      = (const float*)d_in[0];
    const float* x_mask = (const float*)d_in[1];
    const float* c      = (const float*)d_in[2];
    const float* fw     = (const float*)d_in[3];
    const float* fb     = (const float*)d_in[4];
    const float* conv_w = (const float*)d_in[5];
    const float* conv_b = (const float*)d_in[6];
    const float* aux_w  = (const float*)d_in[7];
    const float* out_w  = (const float*)d_in[8];
    const float* out_b  = (const float*)d_in[9];
    const float* w1     = (const float*)d_in[10];
    const float* b1     = (const float*)d_in[11];
    const float* w2     = (const float*)d_in[12];
    const float* b2     = (const float*)d_in[13];

    cudaFuncSetAttribute(k_layer, cudaFuncAttributeMaxDynamicSharedMemorySize,
                         SMEM_LAYER);

    int nprep = NLAYERS * KPACK * 128;
    k_prep<<<(nprep + 511) / 512, 512>>>(conv_w, aux_w, out_w);
    k_first<<<(RCH * NPOS) / 512, 512>>>(x, fw, fb);

    for (int l = 0; l < NLAYERS; l++) {
        int d = 1 << (l % 10);
        k_layer<<<NPOS / POSB, THR, SMEM_LAYER>>>(
            l, d, l & 1, conv_b, out_b, c, x_mask);
    }

    k_last<<<NPOS / 256, 256>>>(w1, b1, w2, b2, (float*)d_out);
}

// round 5
// speedup vs baseline: 1.5644x; 1.5644x over previous
#include <cuda_runtime.h>

#define RCH 64
#define GCH 128
#define ACH 80
#define SCH 64
#define TT 8192
#define BB 8
#define NPOS (BB*TT)          // 65536
#define NLAYERS 30
#define POSB 128              // positions per block
#define THR 512
#define KPACK 336             // 192 conv + 80 aux + 64 out

// smem: wbuf up to 80*64 u64 (40960 B) + xbuf up to 80*128 f32 (40960 B)
#define WBUF_BYTES (80*64*8)
#define SMEM_LAYER (WBUF_BYTES + 80*128*4)   // 81920

__device__ float g_xa[BB*RCH*TT];
__device__ float g_xb[BB*RCH*TT];
__device__ float g_skip[BB*SCH*TT];

typedef unsigned long long ull;

// packed weights: [layer][k][c] = (W[k][c], W[k][c+64]),
// k: 0..191 conv (tap*64+ci), 192..271 aux j, 272..335 out j ; c = 0..63
__device__ ull g_pk[(size_t)NLAYERS * KPACK * 64];

static __device__ __forceinline__ ull pk2(float lo, float hi) {
    ull r; asm("mov.b64 %0, {%1, %2};" : "=l"(r) : "f"(lo), "f"(hi)); return r;
}
static __device__ __forceinline__ void upk2(ull v, float& lo, float& hi) {
    asm("mov.b64 {%0, %1}, %2;" : "=f"(lo), "=f"(hi) : "l"(v));
}
static __device__ __forceinline__ void fma2(ull& acc, ull w, ull x) {
    asm("fma.rn.f32x2 %0, %1, %2, %0;" : "+l"(acc) : "l"(w), "l"(x));
}
static __device__ __forceinline__ float tanhapx(float x) {
    float r; asm("tanh.approx.f32 %0, %1;" : "=f"(r) : "f"(x)); return r;
}
static __device__ __forceinline__ float gatef(float a, float b) {
    return tanhapx(a) * (0.5f * tanhapx(0.5f * b) + 0.5f);
}

// ---------------------------------------------------------------------------
// one-shot weight repack into gate-pair u64 layout
// ---------------------------------------------------------------------------
__global__ void k_prep(const float* __restrict__ cw, const float* __restrict__ aw,
                       const float* __restrict__ ow) {
    int idx = blockIdx.x * blockDim.x + threadIdx.x;
    if (idx >= NLAYERS * KPACK * 64) return;
    int c = idx & 63;
    int k = (idx >> 6) % KPACK;
    int l = idx / (KPACK * 64);
    float vlo, vhi;
    if (k < 192) {
        int tap = k >> 6, ci = k & 63;
        vlo = cw[((size_t)l * GCH + c) * (RCH * 3) + ci * 3 + tap];
        vhi = cw[((size_t)l * GCH + c + 64) * (RCH * 3) + ci * 3 + tap];
    } else if (k < 272) {
        int j = k - 192;
        vlo = aw[((size_t)l * GCH + c) * ACH + j];
        vhi = aw[((size_t)l * GCH + c + 64) * ACH + j];
    } else {
        int j = k - 272;
        vlo = ow[((size_t)l * GCH + c) * (GCH / 2) + j];
        vhi = ow[((size_t)l * GCH + c + 64) * (GCH / 2) + j];
    }
    g_pk[idx] = pk2(vlo, vhi);
}

// ---------------------------------------------------------------------------
__global__ void k_first(const float* __restrict__ x,
                        const float* __restrict__ fw,
                        const float* __restrict__ fb) {
    int idx = blockIdx.x * blockDim.x + threadIdx.x;
    int r = idx >> 16;
    int p = idx & (NPOS - 1);
    int b = p >> 13;
    int t = p & (TT - 1);
    float v = fw[r] * x[p] + fb[r];
    g_xa[(b * RCH + r) * TT + t] = v;
    g_skip[(b * SCH + r) * TT + t] = 0.f;
}

// ---------------------------------------------------------------------------
// inner GEMM: 16 fma2 per k. w = 2 broadcast LDS.128, x = 1 LDS.128 + dup.
// acc[i][u]: i = ch-pair (c4+i, c4+i+64), u = position 4*lane+u.
// ---------------------------------------------------------------------------
static __device__ __forceinline__ void gemm_acc(ull (&acc)[4][4],
        const ull* __restrict__ wk,      // wbuf + c4
        const float* __restrict__ xk,    // xbuf + 4*lane
        int K) {
#pragma unroll 1
    for (int k0 = 0; k0 < K; k0 += 8) {
        const ull*   w8 = wk + k0 * 64;
        const float* x8 = xk + k0 * 128;
#pragma unroll
        for (int kk = 0; kk < 8; kk++) {
            ulonglong2 w01 = *(const ulonglong2*)(w8 + kk * 64);
            ulonglong2 w23 = *(const ulonglong2*)(w8 + kk * 64 + 2);
            float4 xv = *(const float4*)(x8 + kk * 128);
            ull x0 = pk2(xv.x, xv.x);
            ull x1 = pk2(xv.y, xv.y);
            ull x2 = pk2(xv.z, xv.z);
            ull x3 = pk2(xv.w, xv.w);
            fma2(acc[0][0], (ull)w01.x, x0); fma2(acc[0][1], (ull)w01.x, x1);
            fma2(acc[0][2], (ull)w01.x, x2); fma2(acc[0][3], (ull)w01.x, x3);
            fma2(acc[1][0], (ull)w01.y, x0); fma2(acc[1][1], (ull)w01.y, x1);
            fma2(acc[1][2], (ull)w01.y, x2); fma2(acc[1][3], (ull)w01.y, x3);
            fma2(acc[2][0], (ull)w23.x, x0); fma2(acc[2][1], (ull)w23.x, x1);
            fma2(acc[2][2], (ull)w23.x, x2); fma2(acc[2][3], (ull)w23.x, x3);
            fma2(acc[3][0], (ull)w23.y, x0); fma2(acc[3][1], (ull)w23.y, x1);
            fma2(acc[3][2], (ull)w23.y, x2); fma2(acc[3][3], (ull)w23.y, x3);
        }
    }
}

// ---------------------------------------------------------------------------
// fused layer. warp w owns ch-pairs {4w..4w+3}; lane owns positions
// {4*lane .. 4*lane+3} of the 128-position tile.
// ---------------------------------------------------------------------------
__global__ void __launch_bounds__(THR, 2)
k_layer(int l, int d, int flip,
        const float* __restrict__ conv_b, const float* __restrict__ out_b,
        const float* __restrict__ cond,   const float* __restrict__ mask) {
    extern __shared__ char smraw[];
    ull*   wbuf = (ull*)smraw;                       // [K][64] pairs
    float* xbuf = (float*)(smraw + WBUF_BYTES);      // [K][128] scalars

    const float* xin  = flip ? g_xb : g_xa;
    float*       xout = flip ? g_xa : g_xb;

    const int tid  = threadIdx.x;
    const int wid  = tid >> 5;
    const int lane = tid & 31;
    const int c4   = 4 * wid;
    const int p0   = blockIdx.x * POSB;
    const int b    = p0 >> 13;
    const int tb   = p0 & (TT - 1);

    const ull* pk = g_pk + (size_t)l * KPACK * 64;

    // ===== accumulators (conv bias, gate-pair packed) ========================
    ull acc[4][4];
    const float* cbp = conv_b + l * GCH;
#pragma unroll
    for (int i = 0; i < 4; i++) {
        ull bp = pk2(cbp[c4 + i], cbp[64 + c4 + i]);
#pragma unroll
        for (int u = 0; u < 4; u++) acc[i][u] = bp;
    }

    // ===== dilated conv: 3 taps ==============================================
#pragma unroll 1
    for (int tap = 0; tap < 3; ++tap) {
        const int off = (tap - 1) * d;
        __syncthreads();
        {   // weights: straight memcpy of 64*64 u64
            const ulonglong2* src = (const ulonglong2*)(pk + tap * 64 * 64);
            ulonglong2* dst = (ulonglong2*)wbuf;
#pragma unroll
            for (int r = 0; r < 4; r++) dst[tid + r * THR] = src[tid + r * THR];
        }
        for (int idx = tid; idx < RCH * 64; idx += THR) {
            int ci = idx >> 6, pp = idx & 63;
            const float* xrow = xin + (size_t)(b * RCH + ci) * TT;
            int t0 = tb + 2 * pp + off;
            float2 v;
            v.x = ((unsigned)t0 < TT) ? xrow[t0] : 0.f;
            v.y = ((unsigned)(t0 + 1) < TT) ? xrow[t0 + 1] : 0.f;
            *(float2*)(xbuf + ci * POSB + 2 * pp) = v;
        }
        __syncthreads();
        gemm_acc(acc, wbuf + c4, xbuf + 4 * lane, RCH);
    }

    // ===== aux: single 80-k phase ===========================================
    __syncthreads();
    {
        const ulonglong2* src = (const ulonglong2*)(pk + 192 * 64);
        ulonglong2* dst = (ulonglong2*)wbuf;
#pragma unroll
        for (int r = 0; r < 5; r++) dst[tid + r * THR] = src[tid + r * THR];
    }
    for (int idx = tid; idx < ACH * 64; idx += THR) {
        int j = idx >> 6, pp = idx & 63;
        float2 v = *(const float2*)(cond + (size_t)(b * ACH + j) * TT + tb + 2 * pp);
        *(float2*)(xbuf + j * POSB + 2 * pp) = v;
    }
    __syncthreads();
    gemm_acc(acc, wbuf + c4, xbuf + 4 * lane, ACH);

    // ===== gate -> xbuf (z), stage out weights ==============================
    __syncthreads();
#pragma unroll
    for (int i = 0; i < 4; i++) {
        float4 zv;
        float a, g;
        upk2(acc[i][0], a, g); zv.x = gatef(a, g);
        upk2(acc[i][1], a, g); zv.y = gatef(a, g);
        upk2(acc[i][2], a, g); zv.z = gatef(a, g);
        upk2(acc[i][3], a, g); zv.w = gatef(a, g);
        *(float4*)(xbuf + (c4 + i) * POSB + 4 * lane) = zv;
    }
    {
        const ulonglong2* src = (const ulonglong2*)(pk + 272 * 64);
        ulonglong2* dst = (ulonglong2*)wbuf;
#pragma unroll
        for (int r = 0; r < 4; r++) dst[tid + r * THR] = src[tid + r * THR];
    }
    __syncthreads();

    // ===== out projection: pairs (residual r, skip r) ========================
    ull oacc[4][4];
    const float* obp = out_b + l * (RCH + SCH);
#pragma unroll
    for (int i = 0; i < 4; i++) {
        ull bp = pk2(obp[c4 + i], obp[64 + c4 + i]);
#pragma unroll
        for (int u = 0; u < 4; u++) oacc[i][u] = bp;
    }
    gemm_acc(oacc, wbuf + c4, xbuf + 4 * lane, GCH / 2);

    // ===== mask, residual, skip (float4 paths) ===============================
    const int tpos = tb + 4 * lane;
    float4 mm = *(const float4*)(mask + p0 + 4 * lane);
#pragma unroll
    for (int i = 0; i < 4; i++) {
        float r0, s0, r1, s1, r2, s2, r3, s3;
        upk2(oacc[i][0], r0, s0); upk2(oacc[i][1], r1, s1);
        upk2(oacc[i][2], r2, s2); upk2(oacc[i][3], r3, s3);

        size_t xi = ((size_t)(b * RCH + c4 + i) << 13) + tpos;
        float4 xv = *(const float4*)(xin + xi);
        float4 ov;
        ov.x = fmaf(r0, mm.x, xv.x); ov.y = fmaf(r1, mm.y, xv.y);
        ov.z = fmaf(r2, mm.z, xv.z); ov.w = fmaf(r3, mm.w, xv.w);
        *(float4*)(xout + xi) = ov;

        size_t si = ((size_t)(b * SCH + c4 + i) << 13) + tpos;
        float4 sv = *(const float4*)(g_skip + si);
        float4 so;
        so.x = fmaf(s0, mm.x, sv.x); so.y = fmaf(s1, mm.y, sv.y);
        so.z = fmaf(s2, mm.z, sv.z); so.w = fmaf(s3, mm.w, sv.w);
        *(float4*)(g_skip + si) = so;
    }
}

// ---------------------------------------------------------------------------
__global__ void k_last(const float* __restrict__ w1, const float* __restrict__ b1,
                       const float* __restrict__ w2, const float* __restrict__ b2,
                       float* __restrict__ out) {
    __shared__ float w1t[64 * 64];
    __shared__ float w2s[64];
    __shared__ float b1s[64];
    const int tid = threadIdx.x;
    for (int idx = tid; idx < 64 * 64; idx += 256) {
        int i = idx >> 6, j = idx & 63;
        w1t[i * 64 + j] = w1[j * 64 + i];
    }
    if (tid < 64) { w2s[tid] = w2[tid]; b1s[tid] = b1[tid]; }
    __syncthreads();

    const int p = blockIdx.x * 256 + tid;
    const int b = p >> 13;
    const int t = p & (TT - 1);

    float acc[64];
#pragma unroll
    for (int j = 0; j < 64; j++) acc[j] = b1s[j];

    const float* sp = g_skip + (size_t)b * SCH * TT + t;
    for (int i = 0; i < 64; i++) {
        float sv = fmaxf(sp[i * TT], 0.f);
#pragma unroll
        for (int j = 0; j < 64; j += 4) {
            float4 w = *(const float4*)(w1t + i * 64 + j);
            acc[j]     = fmaf(w.x, sv, acc[j]);
            acc[j + 1] = fmaf(w.y, sv, acc[j + 1]);
            acc[j + 2] = fmaf(w.z, sv, acc[j + 2]);
            acc[j + 3] = fmaf(w.w, sv, acc[j + 3]);
        }
    }
    float y = b2[0];
#pragma unroll
    for (int j = 0; j < 64; j++) y = fmaf(w2s[j], fmaxf(acc[j], 0.f), y);
    out[p] = y;
}

// ---------------------------------------------------------------------------
extern "C" void kernel_launch(void* const* d_in, const int* in_sizes, int n_in,
                              void* d_out, int out_size) {
    const float* x      = (const float*)d_in[0];
    const float* x_mask = (const float*)d_in[1];
    const float* c      = (const float*)d_in[2];
    const float* fw     = (const float*)d_in[3];
    const float* fb     = (const float*)d_in[4];
    const float* conv_w = (const float*)d_in[5];
    const float* conv_b = (const float*)d_in[6];
    const float* aux_w  = (const float*)d_in[7];
    const float* out_w  = (const float*)d_in[8];
    const float* out_b  = (const float*)d_in[9];
    const float* w1     = (const float*)d_in[10];
    const float* b1     = (const float*)d_in[11];
    const float* w2     = (const float*)d_in[12];
    const float* b2     = (const float*)d_in[13];

    cudaFuncSetAttribute(k_layer, cudaFuncAttributeMaxDynamicSharedMemorySize,
                         SMEM_LAYER);

    int nprep = NLAYERS * KPACK * 64;
    k_prep<<<(nprep + 511) / 512, 512>>>(conv_w, aux_w, out_w);
    k_first<<<(RCH * NPOS) / 512, 512>>>(x, fw, fb);

    for (int l = 0; l < NLAYERS; l++) {
        int d = 1 << (l % 10);
        k_layer<<<NPOS / POSB, THR, SMEM_LAYER>>>(
            l, d, l & 1, conv_b, out_b, c, x_mask);
    }

    k_last<<<NPOS / 256, 256>>>(w1, b1, w2, b2, (float*)d_out);
}

// round 6
// speedup vs baseline: 1.5685x; 1.0026x over previous
#include <cuda_runtime.h>

#define RCH 64
#define GCH 128
#define ACH 80
#define SCH 64
#define TT 8192
#define BB 8
#define NPOS (BB*TT)          // 65536
#define NLAYERS 30
#define POSB 128              // positions per block
#define THR 512
#define KPACK 336             // 192 conv + 80 aux + 64 out
#define XSTR 132              // padded floats per x row

#define WBUF_BYTES (80*64*8)                     // 40960
#define SMEM_LAYER (WBUF_BYTES + 80*XSTR*4)      // 83200

__device__ float g_xa[BB*RCH*TT];
__device__ float g_xb[BB*RCH*TT];
__device__ float g_skip[BB*SCH*TT];

typedef unsigned long long ull;

// packed weights: [layer][k][c] = (W[k][c], W[k][c+64]),
// k: 0..191 conv (tap*64+ci), 192..271 aux j, 272..335 out j ; c = 0..63
__device__ ull g_pk[(size_t)NLAYERS * KPACK * 64];

static __device__ __forceinline__ ull pk2(float lo, float hi) {
    ull r; asm("mov.b64 %0, {%1, %2};" : "=l"(r) : "f"(lo), "f"(hi)); return r;
}
static __device__ __forceinline__ void upk2(ull v, float& lo, float& hi) {
    asm("mov.b64 {%0, %1}, %2;" : "=f"(lo), "=f"(hi) : "l"(v));
}
static __device__ __forceinline__ void fma2(ull& acc, ull w, ull x) {
    asm("fma.rn.f32x2 %0, %1, %2, %0;" : "+l"(acc) : "l"(w), "l"(x));
}
static __device__ __forceinline__ float tanhapx(float x) {
    float r; asm("tanh.approx.f32 %0, %1;" : "=f"(r) : "f"(x)); return r;
}
static __device__ __forceinline__ float gatef(float a, float b) {
    return tanhapx(a) * (0.5f * tanhapx(0.5f * b) + 0.5f);
}

// ---------------------------------------------------------------------------
__global__ void k_prep(const float* __restrict__ cw, const float* __restrict__ aw,
                       const float* __restrict__ ow) {
    int idx = blockIdx.x * blockDim.x + threadIdx.x;
    if (idx >= NLAYERS * KPACK * 64) return;
    int c = idx & 63;
    int k = (idx >> 6) % KPACK;
    int l = idx / (KPACK * 64);
    float vlo, vhi;
    if (k < 192) {
        int tap = k >> 6, ci = k & 63;
        vlo = cw[((size_t)l * GCH + c) * (RCH * 3) + ci * 3 + tap];
        vhi = cw[((size_t)l * GCH + c + 64) * (RCH * 3) + ci * 3 + tap];
    } else if (k < 272) {
        int j = k - 192;
        vlo = aw[((size_t)l * GCH + c) * ACH + j];
        vhi = aw[((size_t)l * GCH + c + 64) * ACH + j];
    } else {
        int j = k - 272;
        vlo = ow[((size_t)l * GCH + c) * (GCH / 2) + j];
        vhi = ow[((size_t)l * GCH + c + 64) * (GCH / 2) + j];
    }
    g_pk[idx] = pk2(vlo, vhi);
}

// ---------------------------------------------------------------------------
__global__ void k_first(const float* __restrict__ x,
                        const float* __restrict__ fw,
                        const float* __restrict__ fb) {
    int idx = blockIdx.x * blockDim.x + threadIdx.x;
    int r = idx >> 16;
    int p = idx & (NPOS - 1);
    int b = p >> 13;
    int t = p & (TT - 1);
    float v = fw[r] * x[p] + fb[r];
    g_xa[(b * RCH + r) * TT + t] = v;
    g_skip[(b * SCH + r) * TT + t] = 0.f;
}

// ---------------------------------------------------------------------------
// inner GEMM: 16 fma2 per k per lane.
// wk = wbuf + c4 (lane's 4 ch-pairs), xk = xbuf + lane's 4 positions.
// ---------------------------------------------------------------------------
static __device__ __forceinline__ void gemm_acc(ull (&acc)[4][4],
        const ull* __restrict__ wk, const float* __restrict__ xk, int K) {
#pragma unroll 1
    for (int k0 = 0; k0 < K; k0 += 8) {
        const ull*   w8 = wk + k0 * 64;
        const float* x8 = xk + k0 * XSTR;
#pragma unroll
        for (int kk = 0; kk < 8; kk++) {
            ulonglong2 w01 = *(const ulonglong2*)(w8 + kk * 64);
            ulonglong2 w23 = *(const ulonglong2*)(w8 + kk * 64 + 2);
            float4 xv = *(const float4*)(x8 + kk * XSTR);
            ull x0 = pk2(xv.x, xv.x);
            ull x1 = pk2(xv.y, xv.y);
            ull x2 = pk2(xv.z, xv.z);
            ull x3 = pk2(xv.w, xv.w);
            fma2(acc[0][0], (ull)w01.x, x0); fma2(acc[0][1], (ull)w01.x, x1);
            fma2(acc[0][2], (ull)w01.x, x2); fma2(acc[0][3], (ull)w01.x, x3);
            fma2(acc[1][0], (ull)w01.y, x0); fma2(acc[1][1], (ull)w01.y, x1);
            fma2(acc[1][2], (ull)w01.y, x2); fma2(acc[1][3], (ull)w01.y, x3);
            fma2(acc[2][0], (ull)w23.x, x0); fma2(acc[2][1], (ull)w23.x, x1);
            fma2(acc[2][2], (ull)w23.x, x2); fma2(acc[2][3], (ull)w23.x, x3);
            fma2(acc[3][0], (ull)w23.y, x0); fma2(acc[3][1], (ull)w23.y, x1);
            fma2(acc[3][2], (ull)w23.y, x2); fma2(acc[3][3], (ull)w23.y, x3);
        }
    }
}

// ---------------------------------------------------------------------------
// fused layer. warp (ph = wid>>3, cq = wid&7): position-half ph, ch-quad cq.
// lane (pg = lane&15, cg = lane>>4): 4 positions 64*ph+4*pg, 4 ch-pairs
// c4 = 8*cq + 4*cg.
// ---------------------------------------------------------------------------
__global__ void __launch_bounds__(THR, 2)
k_layer(int l, int d, int flip,
        const float* __restrict__ conv_b, const float* __restrict__ out_b,
        const float* __restrict__ cond,   const float* __restrict__ mask) {
    extern __shared__ char smraw[];
    ull*   wbuf = (ull*)smraw;                       // [K][64] pairs
    float* xbuf = (float*)(smraw + WBUF_BYTES);      // [K][XSTR]

    const float* xin  = flip ? g_xb : g_xa;
    float*       xout = flip ? g_xa : g_xb;

    const int tid  = threadIdx.x;
    const int wid  = tid >> 5;
    const int lane = tid & 31;
    const int ph   = wid >> 3;
    const int cq   = wid & 7;
    const int pg   = lane & 15;
    const int cg   = lane >> 4;
    const int c4   = 8 * cq + 4 * cg;
    const int pl   = 64 * ph + 4 * pg;     // lane's base position in tile
    const int p0   = blockIdx.x * POSB;
    const int b    = p0 >> 13;
    const int tb   = p0 & (TT - 1);

    const ull* pk = g_pk + (size_t)l * KPACK * 64;

    // ===== accumulators (conv bias, gate-pair packed) ========================
    ull acc[4][4];
    const float* cbp = conv_b + l * GCH;
#pragma unroll
    for (int i = 0; i < 4; i++) {
        ull bp = pk2(cbp[c4 + i], cbp[64 + c4 + i]);
#pragma unroll
        for (int u = 0; u < 4; u++) acc[i][u] = bp;
    }

    // ===== dilated conv: 3 taps ==============================================
#pragma unroll 1
    for (int tap = 0; tap < 3; ++tap) {
        const int off = (tap - 1) * d;
        __syncthreads();
        {   // weights: straight memcpy of 64*64 u64
            const ulonglong2* src = (const ulonglong2*)(pk + tap * 64 * 64);
            ulonglong2* dst = (ulonglong2*)wbuf;
#pragma unroll
            for (int r = 0; r < 4; r++) dst[tid + r * THR] = src[tid + r * THR];
        }
        for (int idx = tid; idx < RCH * POSB; idx += THR) {
            int ci = idx >> 7, pp = idx & 127;
            int t0 = tb + pp + off;
            xbuf[ci * XSTR + pp] = ((unsigned)t0 < TT)
                ? xin[(size_t)(b * RCH + ci) * TT + t0] : 0.f;
        }
        __syncthreads();
        gemm_acc(acc, wbuf + c4, xbuf + pl, RCH);
    }

    // ===== aux: single 80-k phase ===========================================
    __syncthreads();
    {
        const ulonglong2* src = (const ulonglong2*)(pk + 192 * 64);
        ulonglong2* dst = (ulonglong2*)wbuf;
#pragma unroll
        for (int r = 0; r < 5; r++) dst[tid + r * THR] = src[tid + r * THR];
    }
    for (int idx = tid; idx < ACH * POSB; idx += THR) {
        int j = idx >> 7, pp = idx & 127;
        xbuf[j * XSTR + pp] = cond[(size_t)(b * ACH + j) * TT + tb + pp];
    }
    __syncthreads();
    gemm_acc(acc, wbuf + c4, xbuf + pl, ACH);

    // ===== gate -> xbuf (z rows), stage out weights =========================
    __syncthreads();
#pragma unroll
    for (int i = 0; i < 4; i++) {
        float4 zv;
        float a, g;
        upk2(acc[i][0], a, g); zv.x = gatef(a, g);
        upk2(acc[i][1], a, g); zv.y = gatef(a, g);
        upk2(acc[i][2], a, g); zv.z = gatef(a, g);
        upk2(acc[i][3], a, g); zv.w = gatef(a, g);
        *(float4*)(xbuf + (c4 + i) * XSTR + pl) = zv;
    }
    {
        const ulonglong2* src = (const ulonglong2*)(pk + 272 * 64);
        ulonglong2* dst = (ulonglong2*)wbuf;
#pragma unroll
        for (int r = 0; r < 4; r++) dst[tid + r * THR] = src[tid + r * THR];
    }
    __syncthreads();

    // ===== out projection: pairs (residual r, skip r) ========================
    ull oacc[4][4];
    const float* obp = out_b + l * (RCH + SCH);
#pragma unroll
    for (int i = 0; i < 4; i++) {
        ull bp = pk2(obp[c4 + i], obp[64 + c4 + i]);
#pragma unroll
        for (int u = 0; u < 4; u++) oacc[i][u] = bp;
    }
    gemm_acc(oacc, wbuf + c4, xbuf + pl, GCH / 2);

    // ===== mask, residual, skip (float4 paths) ===============================
    const int tpos = tb + pl;
    float4 mm = *(const float4*)(mask + p0 + pl);
#pragma unroll
    for (int i = 0; i < 4; i++) {
        float r0, s0, r1, s1, r2, s2, r3, s3;
        upk2(oacc[i][0], r0, s0); upk2(oacc[i][1], r1, s1);
        upk2(oacc[i][2], r2, s2); upk2(oacc[i][3], r3, s3);

        size_t xi = ((size_t)(b * RCH + c4 + i) << 13) + tpos;
        float4 xv = *(const float4*)(xin + xi);
        float4 ov;
        ov.x = fmaf(r0, mm.x, xv.x); ov.y = fmaf(r1, mm.y, xv.y);
        ov.z = fmaf(r2, mm.z, xv.z); ov.w = fmaf(r3, mm.w, xv.w);
        *(float4*)(xout + xi) = ov;

        size_t si = ((size_t)(b * SCH + c4 + i) << 13) + tpos;
        float4 sv = *(const float4*)(g_skip + si);
        float4 so;
        so.x = fmaf(s0, mm.x, sv.x); so.y = fmaf(s1, mm.y, sv.y);
        so.z = fmaf(s2, mm.z, sv.z); so.w = fmaf(s3, mm.w, sv.w);
        *(float4*)(g_skip + si) = so;
    }
}

// ---------------------------------------------------------------------------
__global__ void k_last(const float* __restrict__ w1, const float* __restrict__ b1,
                       const float* __restrict__ w2, const float* __restrict__ b2,
                       float* __restrict__ out) {
    __shared__ float w1t[64 * 64];
    __shared__ float w2s[64];
    __shared__ float b1s[64];
    const int tid = threadIdx.x;
    for (int idx = tid; idx < 64 * 64; idx += 256) {
        int i = idx >> 6, j = idx & 63;
        w1t[i * 64 + j] = w1[j * 64 + i];
    }
    if (tid < 64) { w2s[tid] = w2[tid]; b1s[tid] = b1[tid]; }
    __syncthreads();

    const int p = blockIdx.x * 256 + tid;
    const int b = p >> 13;
    const int t = p & (TT - 1);

    float acc[64];
#pragma unroll
    for (int j = 0; j < 64; j++) acc[j] = b1s[j];

    const float* sp = g_skip + (size_t)b * SCH * TT + t;
    for (int i = 0; i < 64; i++) {
        float sv = fmaxf(sp[i * TT], 0.f);
#pragma unroll
        for (int j = 0; j < 64; j += 4) {
            float4 w = *(const float4*)(w1t + i * 64 + j);
            acc[j]     = fmaf(w.x, sv, acc[j]);
            acc[j + 1] = fmaf(w.y, sv, acc[j + 1]);
            acc[j + 2] = fmaf(w.z, sv, acc[j + 2]);
            acc[j + 3] = fmaf(w.w, sv, acc[j + 3]);
        }
    }
    float y = b2[0];
#pragma unroll
    for (int j = 0; j < 64; j++) y = fmaf(w2s[j], fmaxf(acc[j], 0.f), y);
    out[p] = y;
}

// ---------------------------------------------------------------------------
extern "C" void kernel_launch(void* const* d_in, const int* in_sizes, int n_in,
                              void* d_out, int out_size) {
    const float* x      = (const float*)d_in[0];
    const float* x_mask = (const float*)d_in[1];
    const float* c      = (const float*)d_in[2];
    const float* fw     = (const float*)d_in[3];
    const float* fb     = (const float*)d_in[4];
    const float* conv_w = (const float*)d_in[5];
    const float* conv_b = (const float*)d_in[6];
    const float* aux_w  = (const float*)d_in[7];
    const float* out_w  = (const float*)d_in[8];
    const float* out_b  = (const float*)d_in[9];
    const float* w1     = (const float*)d_in[10];
    const float* b1     = (const float*)d_in[11];
    const float* w2     = (const float*)d_in[12];
    const float* b2     = (const float*)d_in[13];

    cudaFuncSetAttribute(k_layer, cudaFuncAttributeMaxDynamicSharedMemorySize,
                         SMEM_LAYER);

    int nprep = NLAYERS * KPACK * 64;
    k_prep<<<(nprep + 511) / 512, 512>>>(conv_w, aux_w, out_w);
    k_first<<<(RCH * NPOS) / 512, 512>>>(x, fw, fb);

    for (int l = 0; l < NLAYERS; l++) {
        int d = 1 << (l % 10);
        k_layer<<<NPOS / POSB, THR, SMEM_LAYER>>>(
            l, d, l & 1, conv_b, out_b, c, x_mask);
    }

    k_last<<<NPOS / 256, 256>>>(w1, b1, w2, b2, (float*)d_out);
}

// round 8
// speedup vs baseline: 1.6372x; 1.0438x over previous
#include <cuda_runtime.h>
#include <cuda_bf16.h>
#include <cstdint>
#include <mma.h>
using namespace nvcuda;

#define RCH 64
#define GCH 128
#define ACH 80
#define SCH 64
#define TT 8192
#define BB 8
#define NPOS (BB*TT)          // 65536
#define NLAYERS 30
#define NT 64                 // positions per block tile
#define NPAD 72               // padded position stride (bf16/f32 rows)
#define THR 512
#define WPERL 43008           // 336*128 weights per layer

// smem layout (bytes):
//   [0, 46080)      A region: W chunk staging (hi|lo) / Hsm f32 / OW / Osm
//   [46080, 69120)  B region: X chunk staging (hi|lo) / Z (hi|lo)
#define SM_B_OFF 46080
#define SMEM_TOTAL 69120

__device__ float g_xa[BB*RCH*TT];
__device__ float g_xb[BB*RCH*TT];
__device__ float g_skip[BB*SCH*TT];

// pre-split weights, chunk-contiguous per layer:
// layer base l*WPERL; chunks: tap0 [0,8192), tap1 [8192,16384), tap2 [16384,24576),
// aux [24576,34816) (m*80+kk), out [34816,43008) (m*64+kk)
__device__ __nv_bfloat16 g_wh[(size_t)NLAYERS * WPERL];
__device__ __nv_bfloat16 g_wl[(size_t)NLAYERS * WPERL];

static __device__ __forceinline__ float tanhapx(float x) {
    float r; asm("tanh.approx.f32 %0, %1;" : "=f"(r) : "f"(x)); return r;
}
static __device__ __forceinline__ float gatef(float a, float b) {
    return tanhapx(a) * (0.5f * tanhapx(0.5f * b) + 0.5f);
}

// ---------------------------------------------------------------------------
// one-shot weight split+repack (fp32 -> bf16 hi/lo, chunk layout)
// ---------------------------------------------------------------------------
__global__ void k_prep(const float* __restrict__ cw, const float* __restrict__ aw,
                       const float* __restrict__ ow) {
    int idx = blockIdx.x * blockDim.x + threadIdx.x;
    if (idx >= NLAYERS * WPERL) return;
    int j = idx % WPERL;
    int l = idx / WPERL;
    float v;
    if (j < 24576) {
        int tap = j >> 13, jj = j & 8191;
        int m = jj >> 6, kk = jj & 63;
        v = cw[((size_t)(l * GCH + m) * RCH + kk) * 3 + tap];
    } else if (j < 34816) {
        int jj = j - 24576;
        int m = jj / 80, kk = jj - m * 80;
        v = aw[(size_t)(l * GCH + m) * ACH + kk];
    } else {
        int jj = j - 34816;
        int m = jj >> 6, kk = jj & 63;
        v = ow[(size_t)(l * GCH + m) * 64 + kk];
    }
    __nv_bfloat16 h = __float2bfloat16(v);
    __nv_bfloat16 lo = __float2bfloat16(v - __bfloat162float(h));
    g_wh[idx] = h;
    g_wl[idx] = lo;
}

// ---------------------------------------------------------------------------
__global__ void k_first(const float* __restrict__ x,
                        const float* __restrict__ fw,
                        const float* __restrict__ fb) {
    int idx = blockIdx.x * blockDim.x + threadIdx.x;
    int r = idx >> 16;
    int p = idx & (NPOS - 1);
    int b = p >> 13;
    int t = p & (TT - 1);
    float v = fw[r] * x[p] + fb[r];
    g_xa[(b * RCH + r) * TT + t] = v;
    g_skip[(b * SCH + r) * TT + t] = 0.f;
}

// ---------------------------------------------------------------------------
// fused layer, tensor-core path (bf16x3 wmma).
// warp w: m0 = (w&7)*16, n0 = (w>>3)*32; 2 acc fragments (n0, n0+16).
// ---------------------------------------------------------------------------
__global__ void __launch_bounds__(THR, 2)
k_layer(int l, int d, int flip,
        const float* __restrict__ conv_b, const float* __restrict__ out_b,
        const float* __restrict__ cond,   const float* __restrict__ mask) {
    extern __shared__ char smraw[];
    __nv_bfloat16* wa = (__nv_bfloat16*)smraw;                 // A staging
    __nv_bfloat16* xbh = (__nv_bfloat16*)(smraw + SM_B_OFF);   // B staging hi
    float* fsm = (float*)smraw;                                // H / O overlay

    const float* xin  = flip ? g_xb : g_xa;
    float*       xout = flip ? g_xa : g_xb;

    const int tid  = threadIdx.x;
    const int wid  = tid >> 5;
    const int m0   = (wid & 7) * 16;
    const int n0   = (wid >> 3) * 32;
    const int p0   = blockIdx.x * NT;
    const int b    = p0 >> 13;
    const int tb   = p0 & (TT - 1);

    const __nv_bfloat16* gwh = g_wh + (size_t)l * WPERL;
    const __nv_bfloat16* gwl = g_wl + (size_t)l * WPERL;

    wmma::fragment<wmma::accumulator, 16, 16, 16, float> acc[2];
    wmma::fill_fragment(acc[0], 0.f);
    wmma::fill_fragment(acc[1], 0.f);

    // ===== GEMM1: 4 k-chunks (tap0, tap1, tap2, aux) =========================
#pragma unroll 1
    for (int ch = 0; ch < 4; ch++) {
        const int S    = (ch < 3) ? 64 : 80;
        const int SPAD = (ch < 3) ? 72 : 88;
        const int koff = (ch < 3) ? ch * 8192 : 24576;

        __syncthreads();
        // stage W hi/lo (u32 memcpy, src layout m*S+kk contiguous)
        {
            const unsigned int* sh = (const unsigned int*)(gwh + koff);
            const unsigned int* sl = (const unsigned int*)(gwl + koff);
            unsigned int* dh = (unsigned int*)wa;
            unsigned int* dl = dh + 128 * (SPAD / 2);
            const int s2 = S / 2, sp2 = SPAD / 2;
            for (int idx = tid; idx < 128 * s2; idx += THR) {
                int m = idx / s2, kp = idx - m * s2;
                dh[m * sp2 + kp] = sh[idx];
                dl[m * sp2 + kp] = sl[idx];
            }
        }
        // stage X hi/lo
        {
            __nv_bfloat16* xh = xbh;
            __nv_bfloat16* xl = xbh + S * NPAD;
            if (ch < 3) {
                const int off = (ch - 1) * d;
                for (int idx = tid; idx < 64 * NT; idx += THR) {
                    int kk = idx >> 6, pp = idx & 63;
                    int t0 = tb + pp + off;
                    float v = ((unsigned)t0 < TT)
                        ? xin[(size_t)(b * RCH + kk) * TT + t0] : 0.f;
                    __nv_bfloat16 h = __float2bfloat16(v);
                    __nv_bfloat16 lo = __float2bfloat16(v - __bfloat162float(h));
                    xh[kk * NPAD + pp] = h;
                    xl[kk * NPAD + pp] = lo;
                }
            } else {
                for (int idx = tid; idx < ACH * NT; idx += THR) {
                    int kk = idx >> 6, pp = idx & 63;
                    float v = cond[(size_t)(b * ACH + kk) * TT + tb + pp];
                    __nv_bfloat16 h = __float2bfloat16(v);
                    __nv_bfloat16 lo = __float2bfloat16(v - __bfloat162float(h));
                    xh[kk * NPAD + pp] = h;
                    xl[kk * NPAD + pp] = lo;
                }
            }
        }
        __syncthreads();

        const __nv_bfloat16* wh = wa;
        const __nv_bfloat16* wl = wa + 128 * SPAD;
        const __nv_bfloat16* xh = xbh;
        const __nv_bfloat16* xl = xbh + S * NPAD;
        const int KS = S / 16;
#pragma unroll 1
        for (int ks = 0; ks < KS; ks++) {
            wmma::fragment<wmma::matrix_a, 16, 16, 16, __nv_bfloat16, wmma::row_major> ah, al;
            wmma::load_matrix_sync(ah, wh + m0 * SPAD + 16 * ks, SPAD);
            wmma::load_matrix_sync(al, wl + m0 * SPAD + 16 * ks, SPAD);
#pragma unroll
            for (int nt = 0; nt < 2; nt++) {
                wmma::fragment<wmma::matrix_b, 16, 16, 16, __nv_bfloat16, wmma::row_major> bf;
                const int bo = 16 * ks * NPAD + n0 + 16 * nt;
                wmma::load_matrix_sync(bf, xh + bo, NPAD);
                wmma::mma_sync(acc[nt], ah, bf, acc[nt]);
                wmma::mma_sync(acc[nt], al, bf, acc[nt]);
                wmma::load_matrix_sync(bf, xl + bo, NPAD);
                wmma::mma_sync(acc[nt], ah, bf, acc[nt]);
            }
        }
    }

    // ===== H -> smem, gate -> Z =============================================
    __syncthreads();
    wmma::store_matrix_sync(fsm + m0 * NPAD + n0,      acc[0], NPAD, wmma::mem_row_major);
    wmma::store_matrix_sync(fsm + m0 * NPAD + n0 + 16, acc[1], NPAD, wmma::mem_row_major);
    __syncthreads();
    {
        __nv_bfloat16* zh = xbh;
        __nv_bfloat16* zl = xbh + 64 * NPAD;
        const float* cbp = conv_b + l * GCH;
        for (int idx = tid; idx < 64 * NT; idx += THR) {
            int c = idx >> 6, pp = idx & 63;
            float a = fsm[c * NPAD + pp] + cbp[c];
            float g = fsm[(c + 64) * NPAD + pp] + cbp[c + 64];
            float z = gatef(a, g);
            __nv_bfloat16 h = __float2bfloat16(z);
            __nv_bfloat16 lo = __float2bfloat16(z - __bfloat162float(h));
            zh[c * NPAD + pp] = h;
            zl[c * NPAD + pp] = lo;
        }
    }
    __syncthreads();

    // ===== stage OW over dead Hsm ===========================================
    {
        const unsigned int* sh = (const unsigned int*)(gwh + 34816);
        const unsigned int* sl = (const unsigned int*)(gwl + 34816);
        unsigned int* dh = (unsigned int*)wa;
        unsigned int* dl = dh + 128 * 36;
        for (int idx = tid; idx < 128 * 32; idx += THR) {
            int m = idx >> 5, kp = idx & 31;
            dh[m * 36 + kp] = sh[idx];
            dl[m * 36 + kp] = sl[idx];
        }
    }
    wmma::fill_fragment(acc[0], 0.f);
    wmma::fill_fragment(acc[1], 0.f);
    __syncthreads();

    // ===== GEMM2: out projection (K=64) =====================================
    {
        const __nv_bfloat16* wh = wa;
        const __nv_bfloat16* wl = wa + 128 * 72;
        const __nv_bfloat16* zh = xbh;
        const __nv_bfloat16* zl = xbh + 64 * NPAD;
#pragma unroll 1
        for (int ks = 0; ks < 4; ks++) {
            wmma::fragment<wmma::matrix_a, 16, 16, 16, __nv_bfloat16, wmma::row_major> ah, al;
            wmma::load_matrix_sync(ah, wh + m0 * 72 + 16 * ks, 72);
            wmma::load_matrix_sync(al, wl + m0 * 72 + 16 * ks, 72);
#pragma unroll
            for (int nt = 0; nt < 2; nt++) {
                wmma::fragment<wmma::matrix_b, 16, 16, 16, __nv_bfloat16, wmma::row_major> bf;
                const int bo = 16 * ks * NPAD + n0 + 16 * nt;
                wmma::load_matrix_sync(bf, zh + bo, NPAD);
                wmma::mma_sync(acc[nt], ah, bf, acc[nt]);
                wmma::mma_sync(acc[nt], al, bf, acc[nt]);
                wmma::load_matrix_sync(bf, zl + bo, NPAD);
                wmma::mma_sync(acc[nt], ah, bf, acc[nt]);
            }
        }
    }
    __syncthreads();
    wmma::store_matrix_sync(fsm + m0 * NPAD + n0,      acc[0], NPAD, wmma::mem_row_major);
    wmma::store_matrix_sync(fsm + m0 * NPAD + n0 + 16, acc[1], NPAD, wmma::mem_row_major);
    __syncthreads();

    // ===== epilogue: bias, mask, residual, skip ==============================
    {
        const float* obp = out_b + l * (RCH + SCH);
        for (int idx = tid; idx < 128 * NT; idx += THR) {
            int r = idx >> 6, pp = idx & 63;
            float o = fsm[r * NPAD + pp] + obp[r];
            float m = mask[p0 + pp];
            if (r < RCH) {
                size_t xi = ((size_t)(b * RCH + r) << 13) + tb + pp;
                xout[xi] = fmaf(o, m, xin[xi]);
            } else {
                size_t si = ((size_t)(b * SCH + r - RCH) << 13) + tb + pp;
                g_skip[si] += o * m;
            }
        }
    }
}

// ---------------------------------------------------------------------------
__global__ void k_last(const float* __restrict__ w1, const float* __restrict__ b1,
                       const float* __restrict__ w2, const float* __restrict__ b2,
                       float* __restrict__ out) {
    __shared__ float w1t[64 * 64];
    __shared__ float w2s[64];
    __shared__ float b1s[64];
    const int tid = threadIdx.x;
    for (int idx = tid; idx < 64 * 64; idx += 256) {
        int i = idx >> 6, j = idx & 63;
        w1t[i * 64 + j] = w1[j * 64 + i];
    }
    if (tid < 64) { w2s[tid] = w2[tid]; b1s[tid] = b1[tid]; }
    __syncthreads();

    const int p = blockIdx.x * 256 + tid;
    const int b = p >> 13;
    const int t = p & (TT - 1);

    float acc[64];
#pragma unroll
    for (int j = 0; j < 64; j++) acc[j] = b1s[j];

    const float* sp = g_skip + (size_t)b * SCH * TT + t;
    for (int i = 0; i < 64; i++) {
        float sv = fmaxf(sp[i * TT], 0.f);
#pragma unroll
        for (int j = 0; j < 64; j += 4) {
            float4 w = *(const float4*)(w1t + i * 64 + j);
            acc[j]     = fmaf(w.x, sv, acc[j]);
            acc[j + 1] = fmaf(w.y, sv, acc[j + 1]);
            acc[j + 2] = fmaf(w.z, sv, acc[j + 2]);
            acc[j + 3] = fmaf(w.w, sv, acc[j + 3]);
        }
    }
    float y = b2[0];
#pragma unroll
    for (int j = 0; j < 64; j++) y = fmaf(w2s[j], fmaxf(acc[j], 0.f), y);
    out[p] = y;
}

// ---------------------------------------------------------------------------
extern "C" void kernel_launch(void* const* d_in, const int* in_sizes, int n_in,
                              void* d_out, int out_size) {
    const float* x      = (const float*)d_in[0];
    const float* x_mask = (const float*)d_in[1];
    const float* c      = (const float*)d_in[2];
    const float* fw     = (const float*)d_in[3];
    const float* fb     = (const float*)d_in[4];
    const float* conv_w = (const float*)d_in[5];
    const float* conv_b = (const float*)d_in[6];
    const float* aux_w  = (const float*)d_in[7];
    const float* out_w  = (const float*)d_in[8];
    const float* out_b  = (const float*)d_in[9];
    const float* w1     = (const float*)d_in[10];
    const float* b1     = (const float*)d_in[11];
    const float* w2     = (const float*)d_in[12];
    const float* b2     = (const float*)d_in[13];

    cudaFuncSetAttribute(k_layer, cudaFuncAttributeMaxDynamicSharedMemorySize,
                         SMEM_TOTAL);

    int nprep = NLAYERS * WPERL;
    k_prep<<<(nprep + 511) / 512, 512>>>(conv_w, aux_w, out_w);
    k_first<<<(RCH * NPOS) / 512, 512>>>(x, fw, fb);

    for (int l = 0; l < NLAYERS; l++) {
        int d = 1 << (l % 10);
        k_layer<<<NPOS / NT, THR, SMEM_TOTAL>>>(
            l, d, l & 1, conv_b, out_b, c, x_mask);
    }

    k_last<<<NPOS / 256, 256>>>(w1, b1, w2, b2, (float*)d_out);
}